// round 16
// baseline (speedup 1.0000x reference)
#include <cuda_runtime.h>
#include <cuda_fp16.h>
#include <cstdint>

#define NNODES 50000
#define MAXE   800000
#define IN_DIM 256
#define HID    128
#define OUTD   16
#define EPSB   1e-5f

// ---------------- scratch (static device globals; no allocation) ----------------
__device__ int    g_cnt   [NNODES];
__device__ int    g_rowptr[NNODES + 1];
__device__ int    g_cursor[NNODES];
__device__ int    g_col   [MAXE];
__device__ float  g_dinv  [NNODES];
__device__ float  g_bufA[(size_t)NNODES * HID]; // hW: fp16 (layers 1/2) / fp32 (layer 3)
__device__ float  g_bufB[(size_t)NNODES * HID]; // u, fp32
__device__ float  g_sum  [HID];
__device__ float  g_sq   [HID];
__device__ float  g_scale[HID];
__device__ float  g_shift[HID];
__device__ __half g_Wt1H[128 * 256], g_Wt1L[128 * 256];
__device__ __half g_Wt2H[128 * 128], g_Wt2L[128 * 128];

__device__ __forceinline__ void mma_f16(float* d, const uint32_t* a, const uint32_t* b) {
    asm volatile(
        "mma.sync.aligned.m16n8k16.row.col.f32.f16.f16.f32 "
        "{%0,%1,%2,%3}, {%4,%5,%6,%7}, {%8,%9}, {%0,%1,%2,%3};"
        : "+f"(d[0]), "+f"(d[1]), "+f"(d[2]), "+f"(d[3])
        : "r"(a[0]), "r"(a[1]), "r"(a[2]), "r"(a[3]), "r"(b[0]), "r"(b[1]));
}

__device__ __forceinline__ uint32_t smem_u32(const void* p) {
    return (uint32_t)__cvta_generic_to_shared(p);
}
__device__ __forceinline__ void cp_async16(uint32_t dst, const void* src, bool valid) {
    int sz = valid ? 16 : 0;
    asm volatile("cp.async.cg.shared.global [%0], [%1], 16, %2;"
                 :: "r"(dst), "l"(src), "r"(sz));
}
__device__ __forceinline__ void cp_commit() { asm volatile("cp.async.commit_group;"); }
__device__ __forceinline__ void cp_wait0()  { asm volatile("cp.async.wait_group 0;" ::: "memory"); }

__device__ __forceinline__ void split2(float2 f, uint32_t& hi, uint32_t& lo) {
    __half2 h = __floats2half2_rn(f.x, f.y);
    float2 hf = __half22float2(h);
    __half2 l = __floats2half2_rn(f.x - hf.x, f.y - hf.y);
    hi = *(uint32_t*)&h;
    lo = *(uint32_t*)&l;
}

// ---------------- weight prep ----------------
__global__ void k_prepW(const float* __restrict__ W1, const float* __restrict__ W2) {
    int i = blockIdx.x * blockDim.x + threadIdx.x;
    if (i < 128 * 256) {
        int n = i >> 8, k = i & 255;
        float w = W1[k * 128 + n];
        __half h = __float2half_rn(w);
        g_Wt1H[i] = h;
        g_Wt1L[i] = __float2half_rn(w - __half2float(h));
    }
    if (i < 128 * 128) {
        int n = i >> 7, k = i & 127;
        float w = W2[k * 128 + n];
        __half h = __float2half_rn(w);
        g_Wt2H[i] = h;
        g_Wt2L[i] = __float2half_rn(w - __half2float(h));
    }
}

// ---------------- CSR build ----------------
__global__ void k_zero_cnt(int* cnt, int n) {
    int i = blockIdx.x * blockDim.x + threadIdx.x;
    if (i < n) cnt[i] = 0;
}
__global__ void k_hist(const int* __restrict__ ei, int* cnt, int E) {
    int i = blockIdx.x * blockDim.x + threadIdx.x;
    if (i < E) atomicAdd(&cnt[ei[E + i]], 1);
}
__global__ __launch_bounds__(1024) void k_scan(const int* __restrict__ cnt,
                                               int* rowptr, int* cursor,
                                               float* dinv, int n)
{
    __shared__ int part[1024];
    int tid = threadIdx.x;
    if (tid < HID) { g_sum[tid] = 0.f; g_sq[tid] = 0.f; }
    int chunk = (n + 1023) >> 10;
    int lo = tid * chunk, hi = min(lo + chunk, n);
    int s = 0;
    for (int i = lo; i < hi; i++) s += cnt[i];
    part[tid] = s;
    __syncthreads();
    for (int off = 1; off < 1024; off <<= 1) {
        int v = 0;
        if (tid >= off) v = part[tid - off];
        __syncthreads();
        if (tid >= off) part[tid] += v;
        __syncthreads();
    }
    int run = (tid > 0) ? part[tid - 1] : 0;
    for (int i = lo; i < hi; i++) {
        rowptr[i] = run;
        cursor[i] = run;
        dinv[i] = rsqrtf((float)cnt[i] + 1.0f);
        run += cnt[i];
    }
    if (tid == 1023) rowptr[n] = part[1023];
}
__global__ void k_fill(const int* __restrict__ ei, int* cursor, int* col, int E) {
    int i = blockIdx.x * blockDim.x + threadIdx.x;
    if (i < E) {
        int d = ei[E + i];
        int p = atomicAdd(&cursor[d], 1);
        col[p] = ei[i];
    }
}

// ---------------- fp16-MMA GEMM, cp.async double-buffered ----------------
__global__ __launch_bounds__(256, 2) void k_gemm_hh(
    const float* __restrict__ A,
    const __half* __restrict__ WtH, const __half* __restrict__ WtL,
    __half* __restrict__ T, int nrows, int K, int bn)
{
    __shared__ float  As [2][128][20];
    __shared__ __half WsH[2][128][24];
    __shared__ __half WsL[2][128][24];
    __shared__ float  ssc[IN_DIM], ssh[IN_DIM];

    int tid   = threadIdx.x;
    int lane  = tid & 31;
    int warp  = tid >> 5;
    int warpM = warp >> 1;
    int warpN = warp & 1;
    int g     = lane >> 2;
    int t     = lane & 3;
    int rowBase = blockIdx.x * 128;

    if (bn) {
        for (int f = tid; f < K; f += 256) { ssc[f] = g_scale[f]; ssh[f] = g_shift[f]; }
    }

    float d[2][8][4];
    #pragma unroll
    for (int mt = 0; mt < 2; mt++)
        #pragma unroll
        for (int nt = 0; nt < 8; nt++)
            #pragma unroll
            for (int i = 0; i < 4; i++) d[mt][nt][i] = 0.f;

    int ra = tid >> 2;
    int ca = (tid & 3) << 2;
    int rw = tid >> 1;
    int ow = (tid & 1) << 3;

    {
        int row0 = rowBase + ra, row1 = rowBase + ra + 64;
        cp_async16(smem_u32(&As[0][ra][ca]),      &A[(size_t)row0 * K + ca], row0 < nrows);
        cp_async16(smem_u32(&As[0][ra + 64][ca]), &A[(size_t)row1 * K + ca], row1 < nrows);
        cp_async16(smem_u32(&WsH[0][rw][ow]),     &WtH[(size_t)rw * K + ow], true);
        cp_async16(smem_u32(&WsL[0][rw][ow]),     &WtL[(size_t)rw * K + ow], true);
        cp_commit();
    }

    int ntiles = K >> 4;
    for (int tile = 0; tile < ntiles; tile++) {
        int buf = tile & 1;
        cp_wait0();
        __syncthreads();

        if (tile + 1 < ntiles) {
            int k0n = (tile + 1) << 4;
            int nb  = buf ^ 1;
            int row0 = rowBase + ra, row1 = rowBase + ra + 64;
            cp_async16(smem_u32(&As[nb][ra][ca]),      &A[(size_t)row0 * K + k0n + ca], row0 < nrows);
            cp_async16(smem_u32(&As[nb][ra + 64][ca]), &A[(size_t)row1 * K + k0n + ca], row1 < nrows);
            cp_async16(smem_u32(&WsH[nb][rw][ow]),     &WtH[(size_t)rw * K + k0n + ow], true);
            cp_async16(smem_u32(&WsL[nb][rw][ow]),     &WtL[(size_t)rw * K + k0n + ow], true);
            cp_commit();
        }

        int k0 = tile << 4;
        uint32_t ah[2][4], al[2][4];
        #pragma unroll
        for (int mt = 0; mt < 2; mt++) {
            int m = warpM * 32 + mt * 16 + g;
            float2 f0 = *(float2*)&As[buf][m    ][2 * t];
            float2 f1 = *(float2*)&As[buf][m + 8][2 * t];
            float2 f2 = *(float2*)&As[buf][m    ][2 * t + 8];
            float2 f3 = *(float2*)&As[buf][m + 8][2 * t + 8];
            if (bn) {
                int ka = k0 + 2 * t, kb = ka + 8;
                float sc0 = ssc[ka], sh0 = ssh[ka];
                float sc1 = ssc[ka + 1], sh1 = ssh[ka + 1];
                float sc2 = ssc[kb], sh2 = ssh[kb];
                float sc3 = ssc[kb + 1], sh3 = ssh[kb + 1];
                f0.x = fmaxf(f0.x * sc0 + sh0, 0.f); f0.y = fmaxf(f0.y * sc1 + sh1, 0.f);
                f1.x = fmaxf(f1.x * sc0 + sh0, 0.f); f1.y = fmaxf(f1.y * sc1 + sh1, 0.f);
                f2.x = fmaxf(f2.x * sc2 + sh2, 0.f); f2.y = fmaxf(f2.y * sc3 + sh3, 0.f);
                f3.x = fmaxf(f3.x * sc2 + sh2, 0.f); f3.y = fmaxf(f3.y * sc3 + sh3, 0.f);
            }
            split2(f0, ah[mt][0], al[mt][0]);
            split2(f1, ah[mt][1], al[mt][1]);
            split2(f2, ah[mt][2], al[mt][2]);
            split2(f3, ah[mt][3], al[mt][3]);
        }
        #pragma unroll
        for (int nt = 0; nt < 8; nt++) {
            int n = warpN * 64 + nt * 8 + g;
            uint32_t bh[2], bl[2];
            bh[0] = *(uint32_t*)&WsH[buf][n][2 * t];
            bh[1] = *(uint32_t*)&WsH[buf][n][2 * t + 8];
            bl[0] = *(uint32_t*)&WsL[buf][n][2 * t];
            bl[1] = *(uint32_t*)&WsL[buf][n][2 * t + 8];
            #pragma unroll
            for (int mt = 0; mt < 2; mt++) {
                mma_f16(d[mt][nt], ah[mt], bh);
                mma_f16(d[mt][nt], al[mt], bh);
                mma_f16(d[mt][nt], ah[mt], bl);
            }
        }
    }

    #pragma unroll
    for (int mt = 0; mt < 2; mt++) {
        int r0 = rowBase + warpM * 32 + mt * 16 + g;
        int r1 = r0 + 8;
        #pragma unroll
        for (int nt = 0; nt < 8; nt++) {
            int c = warpN * 64 + nt * 8 + 2 * t;
            if (r0 < nrows)
                *(__half2*)&T[(size_t)r0 * 128 + c] = __floats2half2_rn(d[mt][nt][0], d[mt][nt][1]);
            if (r1 < nrows)
                *(__half2*)&T[(size_t)r1 * 128 + c] = __floats2half2_rn(d[mt][nt][2], d[mt][nt][3]);
        }
    }
}

// ---------------- finalize BN stats ----------------
__global__ void k_finalize_stats(const float* __restrict__ gam,
                                 const float* __restrict__ bet, int nrows)
{
    int f = threadIdx.x;
    float inv_n = 1.0f / (float)nrows;
    float m = g_sum[f] * inv_n;
    float v = g_sq[f] * inv_n - m * m;
    float istd = rsqrtf(v + EPSB);
    float sc = istd * gam[f];
    g_scale[f] = sc;
    g_shift[f] = bet[f] - m * sc;
    g_sum[f] = 0.f;
    g_sq [f] = 0.f;
}

// ---------------- CSR aggregation (HID=128), fp16 rows, 16-deep MLP ----------------
__global__ __launch_bounds__(256) void k_agg128(
    const int* __restrict__ rowptr, const int* __restrict__ col,
    const __half* __restrict__ T, const float* __restrict__ dinv,
    const float* __restrict__ b, float* __restrict__ U, int n)
{
    const uint2* T2 = (const uint2*)T;
    int lane   = threadIdx.x & 31;
    int warp   = (blockIdx.x * blockDim.x + threadIdx.x) >> 5;
    int nwarps = (gridDim.x * blockDim.x) >> 5;
    float4 bb  = *(const float4*)&b[lane * 4];

    float4 s4 = make_float4(0.f, 0.f, 0.f, 0.f);
    float4 q4 = make_float4(0.f, 0.f, 0.f, 0.f);

    for (int node = warp; node < n; node += nwarps) {
        int beg = rowptr[node], end = rowptr[node + 1];
        float dn = dinv[node];
        uint2 sv = T2[(size_t)node * 32 + lane];
        float2 sf0 = __half22float2(*(__half2*)&sv.x);
        float2 sf1 = __half22float2(*(__half2*)&sv.y);
        float4 a0 = make_float4(dn * sf0.x, dn * sf0.y, dn * sf1.x, dn * sf1.y);
        float4 a1 = make_float4(0.f, 0.f, 0.f, 0.f);
        float4 a2 = make_float4(0.f, 0.f, 0.f, 0.f);
        float4 a3 = make_float4(0.f, 0.f, 0.f, 0.f);
        int e = beg;
        // 16-deep unroll: 16 independent row gathers in flight per warp
        for (; e + 15 < end; e += 16) {
            int   ix[16];
            float dv[16];
            uint2 rv[16];
            #pragma unroll
            for (int j = 0; j < 16; j++) ix[j] = col[e + j];
            #pragma unroll
            for (int j = 0; j < 16; j++) dv[j] = dinv[ix[j]];
            #pragma unroll
            for (int j = 0; j < 16; j++) rv[j] = T2[(size_t)ix[j] * 32 + lane];
            #define ACC(A_, j) { \
                float2 f0_ = __half22float2(*(__half2*)&rv[j].x); \
                float2 f1_ = __half22float2(*(__half2*)&rv[j].y); \
                A_.x += dv[j] * f0_.x; A_.y += dv[j] * f0_.y; \
                A_.z += dv[j] * f1_.x; A_.w += dv[j] * f1_.y; }
            ACC(a0, 0)  ACC(a0, 1)  ACC(a0, 2)  ACC(a0, 3)
            ACC(a1, 4)  ACC(a1, 5)  ACC(a1, 6)  ACC(a1, 7)
            ACC(a2, 8)  ACC(a2, 9)  ACC(a2, 10) ACC(a2, 11)
            ACC(a3, 12) ACC(a3, 13) ACC(a3, 14) ACC(a3, 15)
            #undef ACC
        }
        // 4-wide remainder
        for (; e + 3 < end; e += 4) {
            int   ix[4];
            float dv[4];
            uint2 rv[4];
            #pragma unroll
            for (int j = 0; j < 4; j++) ix[j] = col[e + j];
            #pragma unroll
            for (int j = 0; j < 4; j++) dv[j] = dinv[ix[j]];
            #pragma unroll
            for (int j = 0; j < 4; j++) rv[j] = T2[(size_t)ix[j] * 32 + lane];
            #pragma unroll
            for (int j = 0; j < 4; j++) {
                float2 f0_ = __half22float2(*(__half2*)&rv[j].x);
                float2 f1_ = __half22float2(*(__half2*)&rv[j].y);
                a0.x += dv[j] * f0_.x; a0.y += dv[j] * f0_.y;
                a0.z += dv[j] * f1_.x; a0.w += dv[j] * f1_.y;
            }
        }
        for (; e < end; e++) {
            int i0 = col[e];
            float d0 = dinv[i0];
            uint2 rvs = T2[(size_t)i0 * 32 + lane];
            float2 f0_ = __half22float2(*(__half2*)&rvs.x);
            float2 f1_ = __half22float2(*(__half2*)&rvs.y);
            a0.x += d0 * f0_.x; a0.y += d0 * f0_.y;
            a0.z += d0 * f1_.x; a0.w += d0 * f1_.y;
        }
        a0.x += a1.x + a2.x + a3.x;
        a0.y += a1.y + a2.y + a3.y;
        a0.z += a1.z + a2.z + a3.z;
        a0.w += a1.w + a2.w + a3.w;

        float4 u = make_float4(a0.x * dn + bb.x, a0.y * dn + bb.y,
                               a0.z * dn + bb.z, a0.w * dn + bb.w);
        *(float4*)&U[(size_t)node * 128 + lane * 4] = u;
        s4.x += u.x; s4.y += u.y; s4.z += u.z; s4.w += u.w;
        q4.x += u.x * u.x; q4.y += u.y * u.y; q4.z += u.z * u.z; q4.w += u.w * u.w;
    }

    __shared__ float ss[128], sq[128];
    int t = threadIdx.x;
    if (t < 128) { ss[t] = 0.f; sq[t] = 0.f; }
    __syncthreads();
    int f = lane * 4;
    atomicAdd(&ss[f + 0], s4.x); atomicAdd(&sq[f + 0], q4.x);
    atomicAdd(&ss[f + 1], s4.y); atomicAdd(&sq[f + 1], q4.y);
    atomicAdd(&ss[f + 2], s4.z); atomicAdd(&sq[f + 2], q4.z);
    atomicAdd(&ss[f + 3], s4.w); atomicAdd(&sq[f + 3], q4.w);
    __syncthreads();
    if (t < 128) {
        atomicAdd(&g_sum[t], ss[t]);
        atomicAdd(&g_sq [t], sq[t]);
    }
}

// ---------------- layer-3 GEMM (128 -> 16): BN+ReLU fused; fp32 ----------------
__global__ __launch_bounds__(256) void k_gemm16(const float* __restrict__ A,
                                                const float* __restrict__ W,
                                                float* __restrict__ T, int nrows)
{
    __shared__ float Ws[128][16];
    __shared__ float ssc[128], ssh[128];
    for (int v = threadIdx.x; v < 128 * 16; v += blockDim.x)
        Ws[v >> 4][v & 15] = W[v];
    if (threadIdx.x < 128) {
        ssc[threadIdx.x] = g_scale[threadIdx.x];
        ssh[threadIdx.x] = g_shift[threadIdx.x];
    }
    __syncthreads();

    int row = blockIdx.x * blockDim.x + threadIdx.x;
    if (row >= nrows) return;
    float acc[16];
    #pragma unroll
    for (int c = 0; c < 16; c++) acc[c] = 0.f;

    const float4* ar = (const float4*)&A[(size_t)row * 128];
    #pragma unroll 4
    for (int k4 = 0; k4 < 32; k4++) {
        float4 x = ar[k4];
        int k = k4 * 4;
        x.x = fmaxf(x.x * ssc[k + 0] + ssh[k + 0], 0.f);
        x.y = fmaxf(x.y * ssc[k + 1] + ssh[k + 1], 0.f);
        x.z = fmaxf(x.z * ssc[k + 2] + ssh[k + 2], 0.f);
        x.w = fmaxf(x.w * ssc[k + 3] + ssh[k + 3], 0.f);
        #pragma unroll
        for (int c = 0; c < 16; c++)
            acc[c] += x.x * Ws[k][c] + x.y * Ws[k + 1][c]
                    + x.z * Ws[k + 2][c] + x.w * Ws[k + 3][c];
    }
    #pragma unroll
    for (int c = 0; c < 16; c += 4)
        *(float4*)&T[(size_t)row * 16 + c] =
            make_float4(acc[c], acc[c + 1], acc[c + 2], acc[c + 3]);
}

// ---------------- CSR aggregation (OUTD=16), fp32 ----------------
__global__ void k_agg16(const int* __restrict__ rowptr, const int* __restrict__ col,
                        const float* __restrict__ T, const float* __restrict__ dinv,
                        const float* __restrict__ b3, float* __restrict__ out, int n)
{
    int idx = blockIdx.x * blockDim.x + threadIdx.x;
    if (idx >= n * 4) return;
    int node = idx >> 2;
    int gp   = (idx & 3) * 4;
    float4 bb = *(const float4*)&b3[gp];

    int beg = rowptr[node], end = rowptr[node + 1];
    float dn = dinv[node];
    float4 tv = *(const float4*)&T[(size_t)node * 16 + gp];
    float4 acc = make_float4(dn * tv.x, dn * tv.y, dn * tv.z, dn * tv.w);
    int e = beg;
    for (; e + 3 < end; e += 4) {
        int s0 = col[e], s1 = col[e + 1], s2 = col[e + 2], s3 = col[e + 3];
        float d0 = dinv[s0], d1 = dinv[s1], d2 = dinv[s2], d3 = dinv[s3];
        float4 v0 = *(const float4*)&T[(size_t)s0 * 16 + gp];
        float4 v1 = *(const float4*)&T[(size_t)s1 * 16 + gp];
        float4 v2 = *(const float4*)&T[(size_t)s2 * 16 + gp];
        float4 v3 = *(const float4*)&T[(size_t)s3 * 16 + gp];
        acc.x += d0 * v0.x + d1 * v1.x + d2 * v2.x + d3 * v3.x;
        acc.y += d0 * v0.y + d1 * v1.y + d2 * v2.y + d3 * v3.y;
        acc.z += d0 * v0.z + d1 * v1.z + d2 * v2.z + d3 * v3.z;
        acc.w += d0 * v0.w + d1 * v1.w + d2 * v2.w + d3 * v3.w;
    }
    for (; e < end; e++) {
        int s = col[e];
        float d0 = dinv[s];
        float4 v = *(const float4*)&T[(size_t)s * 16 + gp];
        acc.x += d0 * v.x; acc.y += d0 * v.y; acc.z += d0 * v.z; acc.w += d0 * v.w;
    }
    *(float4*)&out[(size_t)node * 16 + gp] =
        make_float4(acc.x * dn + bb.x, acc.y * dn + bb.y,
                    acc.z * dn + bb.z, acc.w * dn + bb.w);
}

// ---------------- launch ----------------
extern "C" void kernel_launch(void* const* d_in, const int* in_sizes, int n_in,
                              void* d_out, int out_size)
{
    const float* x   = (const float*)d_in[0];
    const int*   ei  = (const int*)d_in[1];
    const float* W1  = (const float*)d_in[2];
    const float* b1  = (const float*)d_in[3];
    const float* g1  = (const float*)d_in[4];
    const float* be1 = (const float*)d_in[5];
    const float* W2  = (const float*)d_in[6];
    const float* b2  = (const float*)d_in[7];
    const float* g2  = (const float*)d_in[8];
    const float* be2 = (const float*)d_in[9];
    const float* W3  = (const float*)d_in[10];
    const float* b3  = (const float*)d_in[11];
    float*       out = (float*)d_out;

    int n = in_sizes[0] / IN_DIM;   // 50000
    int E = in_sizes[1] / 2;        // 800000

    int *cnt, *rowptr, *cursor, *col;
    float *dinv, *bufA, *bufB;
    __half *wt1h, *wt1l, *wt2h, *wt2l;
    cudaGetSymbolAddress((void**)&cnt,    g_cnt);
    cudaGetSymbolAddress((void**)&rowptr, g_rowptr);
    cudaGetSymbolAddress((void**)&cursor, g_cursor);
    cudaGetSymbolAddress((void**)&col,    g_col);
    cudaGetSymbolAddress((void**)&dinv,   g_dinv);
    cudaGetSymbolAddress((void**)&bufA,   g_bufA);
    cudaGetSymbolAddress((void**)&bufB,   g_bufB);
    cudaGetSymbolAddress((void**)&wt1h,   g_Wt1H);
    cudaGetSymbolAddress((void**)&wt1l,   g_Wt1L);
    cudaGetSymbolAddress((void**)&wt2h,   g_Wt2H);
    cudaGetSymbolAddress((void**)&wt2l,   g_Wt2L);
    __half* bufAh = (__half*)bufA;

    static cudaStream_t side = nullptr;
    static cudaEvent_t evFork = nullptr, evJoin = nullptr;
    if (side == nullptr) {
        cudaStreamCreateWithFlags(&side, cudaStreamNonBlocking);
        cudaEventCreateWithFlags(&evFork, cudaEventDisableTiming);
        cudaEventCreateWithFlags(&evJoin, cudaEventDisableTiming);
    }

    const int T256 = 256;
    int nb_n    = (n + T256 - 1) / T256;
    int nb_e    = (E + T256 - 1) / T256;
    int nb_rows = (n + 127) / 128;          // 391
    int nb_a16  = (n * 4 + T256 - 1) / T256;
    const int AGG_BLOCKS = 888;

    // fork: CSR build on side stream
    cudaEventRecord(evFork, 0);
    cudaStreamWaitEvent(side, evFork, 0);
    k_zero_cnt<<<nb_n, T256, 0, side>>>(cnt, n);
    k_hist    <<<nb_e, T256, 0, side>>>(ei, cnt, E);
    k_scan    <<<1, 1024, 0, side>>>(cnt, rowptr, cursor, dinv, n);
    k_fill    <<<nb_e, T256, 0, side>>>(ei, cursor, col, E);
    cudaEventRecord(evJoin, side);

    // weight prep (main stream, before gemm1)
    k_prepW<<<128, 256>>>(W1, W2);

    // ---- layer 1 ----
    k_gemm_hh<<<nb_rows, 256>>>(x, wt1h, wt1l, bufAh, n, IN_DIM, 0);

    cudaStreamWaitEvent(0, evJoin, 0);
    k_agg128<<<AGG_BLOCKS, 256>>>(rowptr, col, bufAh, dinv, b1, bufB, n);
    k_finalize_stats<<<1, 128>>>(g1, be1, n);

    // ---- layer 2 ----
    k_gemm_hh<<<nb_rows, 256>>>(bufB, wt2h, wt2l, bufAh, n, HID, 1);
    k_agg128 <<<AGG_BLOCKS, 256>>>(rowptr, col, bufAh, dinv, b2, bufB, n);
    k_finalize_stats<<<1, 128>>>(g2, be2, n);

    // ---- layer 3 ----
    k_gemm16<<<nb_n, 256>>>(bufB, W3, bufA, n);
    k_agg16 <<<nb_a16, T256>>>(rowptr, col, bufA, dinv, b3, out, n);
}

// round 17
// speedup vs baseline: 1.1212x; 1.1212x over previous
#include <cuda_runtime.h>
#include <cuda_fp16.h>
#include <cstdint>

#define NNODES 50000
#define MAXE   800000
#define IN_DIM 256
#define HID    128
#define OUTD   16
#define EPSB   1e-5f

// ---------------- scratch (static device globals; no allocation) ----------------
__device__ int    g_cnt   [NNODES];
__device__ int    g_rowptr[NNODES + 1];
__device__ int    g_cursor[NNODES];
__device__ int    g_col   [MAXE];
__device__ float  g_dinv  [NNODES];
__device__ float  g_bufA[(size_t)NNODES * HID]; // hW: fp16 (layers 1/2) / fp32 (layer 3)
__device__ float  g_bufB[(size_t)NNODES * HID]; // u, fp32
__device__ float  g_sum  [HID];
__device__ float  g_sq   [HID];
__device__ float  g_scale[HID];
__device__ float  g_shift[HID];
__device__ __half g_Wt1H[128 * 256], g_Wt1L[128 * 256];
__device__ __half g_Wt2H[128 * 128], g_Wt2L[128 * 128];

__device__ __forceinline__ void mma_f16(float* d, const uint32_t* a, const uint32_t* b) {
    asm volatile(
        "mma.sync.aligned.m16n8k16.row.col.f32.f16.f16.f32 "
        "{%0,%1,%2,%3}, {%4,%5,%6,%7}, {%8,%9}, {%0,%1,%2,%3};"
        : "+f"(d[0]), "+f"(d[1]), "+f"(d[2]), "+f"(d[3])
        : "r"(a[0]), "r"(a[1]), "r"(a[2]), "r"(a[3]), "r"(b[0]), "r"(b[1]));
}

__device__ __forceinline__ uint32_t smem_u32(const void* p) {
    return (uint32_t)__cvta_generic_to_shared(p);
}
__device__ __forceinline__ void cp_async16(uint32_t dst, const void* src, bool valid) {
    int sz = valid ? 16 : 0;
    asm volatile("cp.async.cg.shared.global [%0], [%1], 16, %2;"
                 :: "r"(dst), "l"(src), "r"(sz));
}
__device__ __forceinline__ void cp_commit() { asm volatile("cp.async.commit_group;"); }
__device__ __forceinline__ void cp_wait0()  { asm volatile("cp.async.wait_group 0;" ::: "memory"); }

__device__ __forceinline__ void split2(float2 f, uint32_t& hi, uint32_t& lo) {
    __half2 h = __floats2half2_rn(f.x, f.y);
    float2 hf = __half22float2(h);
    __half2 l = __floats2half2_rn(f.x - hf.x, f.y - hf.y);
    hi = *(uint32_t*)&h;
    lo = *(uint32_t*)&l;
}

// ---------------- weight prep ----------------
__global__ void k_prepW(const float* __restrict__ W1, const float* __restrict__ W2) {
    int i = blockIdx.x * blockDim.x + threadIdx.x;
    if (i < 128 * 256) {
        int n = i >> 8, k = i & 255;
        float w = W1[k * 128 + n];
        __half h = __float2half_rn(w);
        g_Wt1H[i] = h;
        g_Wt1L[i] = __float2half_rn(w - __half2float(h));
    }
    if (i < 128 * 128) {
        int n = i >> 7, k = i & 127;
        float w = W2[k * 128 + n];
        __half h = __float2half_rn(w);
        g_Wt2H[i] = h;
        g_Wt2L[i] = __float2half_rn(w - __half2float(h));
    }
}

// ---------------- CSR build ----------------
__global__ void k_zero_cnt(int* cnt, int n) {
    int i = blockIdx.x * blockDim.x + threadIdx.x;
    if (i < n) cnt[i] = 0;
}
__global__ void k_hist(const int* __restrict__ ei, int* cnt, int E) {
    int i = blockIdx.x * blockDim.x + threadIdx.x;
    if (i < E) atomicAdd(&cnt[ei[E + i]], 1);
}
__global__ __launch_bounds__(1024) void k_scan(const int* __restrict__ cnt,
                                               int* rowptr, int* cursor,
                                               float* dinv, int n)
{
    __shared__ int part[1024];
    int tid = threadIdx.x;
    if (tid < HID) { g_sum[tid] = 0.f; g_sq[tid] = 0.f; }
    int chunk = (n + 1023) >> 10;
    int lo = tid * chunk, hi = min(lo + chunk, n);
    int s = 0;
    for (int i = lo; i < hi; i++) s += cnt[i];
    part[tid] = s;
    __syncthreads();
    for (int off = 1; off < 1024; off <<= 1) {
        int v = 0;
        if (tid >= off) v = part[tid - off];
        __syncthreads();
        if (tid >= off) part[tid] += v;
        __syncthreads();
    }
    int run = (tid > 0) ? part[tid - 1] : 0;
    for (int i = lo; i < hi; i++) {
        rowptr[i] = run;
        cursor[i] = run;
        dinv[i] = rsqrtf((float)cnt[i] + 1.0f);
        run += cnt[i];
    }
    if (tid == 1023) rowptr[n] = part[1023];
}
__global__ void k_fill(const int* __restrict__ ei, int* cursor, int* col, int E) {
    int i = blockIdx.x * blockDim.x + threadIdx.x;
    if (i < E) {
        int d = ei[E + i];
        int p = atomicAdd(&cursor[d], 1);
        col[p] = ei[i];
    }
}

// ---------------- fp16-MMA GEMM, cp.async double-buffered ----------------
__global__ __launch_bounds__(256, 2) void k_gemm_hh(
    const float* __restrict__ A,
    const __half* __restrict__ WtH, const __half* __restrict__ WtL,
    __half* __restrict__ T, int nrows, int K, int bn)
{
    __shared__ float  As [2][128][20];
    __shared__ __half WsH[2][128][24];
    __shared__ __half WsL[2][128][24];
    __shared__ float  ssc[IN_DIM], ssh[IN_DIM];

    int tid   = threadIdx.x;
    int lane  = tid & 31;
    int warp  = tid >> 5;
    int warpM = warp >> 1;
    int warpN = warp & 1;
    int g     = lane >> 2;
    int t     = lane & 3;
    int rowBase = blockIdx.x * 128;

    if (bn) {
        for (int f = tid; f < K; f += 256) { ssc[f] = g_scale[f]; ssh[f] = g_shift[f]; }
    }

    float d[2][8][4];
    #pragma unroll
    for (int mt = 0; mt < 2; mt++)
        #pragma unroll
        for (int nt = 0; nt < 8; nt++)
            #pragma unroll
            for (int i = 0; i < 4; i++) d[mt][nt][i] = 0.f;

    int ra = tid >> 2;
    int ca = (tid & 3) << 2;
    int rw = tid >> 1;
    int ow = (tid & 1) << 3;

    {
        int row0 = rowBase + ra, row1 = rowBase + ra + 64;
        cp_async16(smem_u32(&As[0][ra][ca]),      &A[(size_t)row0 * K + ca], row0 < nrows);
        cp_async16(smem_u32(&As[0][ra + 64][ca]), &A[(size_t)row1 * K + ca], row1 < nrows);
        cp_async16(smem_u32(&WsH[0][rw][ow]),     &WtH[(size_t)rw * K + ow], true);
        cp_async16(smem_u32(&WsL[0][rw][ow]),     &WtL[(size_t)rw * K + ow], true);
        cp_commit();
    }

    int ntiles = K >> 4;
    for (int tile = 0; tile < ntiles; tile++) {
        int buf = tile & 1;
        cp_wait0();
        __syncthreads();

        if (tile + 1 < ntiles) {
            int k0n = (tile + 1) << 4;
            int nb  = buf ^ 1;
            int row0 = rowBase + ra, row1 = rowBase + ra + 64;
            cp_async16(smem_u32(&As[nb][ra][ca]),      &A[(size_t)row0 * K + k0n + ca], row0 < nrows);
            cp_async16(smem_u32(&As[nb][ra + 64][ca]), &A[(size_t)row1 * K + k0n + ca], row1 < nrows);
            cp_async16(smem_u32(&WsH[nb][rw][ow]),     &WtH[(size_t)rw * K + k0n + ow], true);
            cp_async16(smem_u32(&WsL[nb][rw][ow]),     &WtL[(size_t)rw * K + k0n + ow], true);
            cp_commit();
        }

        int k0 = tile << 4;
        uint32_t ah[2][4], al[2][4];
        #pragma unroll
        for (int mt = 0; mt < 2; mt++) {
            int m = warpM * 32 + mt * 16 + g;
            float2 f0 = *(float2*)&As[buf][m    ][2 * t];
            float2 f1 = *(float2*)&As[buf][m + 8][2 * t];
            float2 f2 = *(float2*)&As[buf][m    ][2 * t + 8];
            float2 f3 = *(float2*)&As[buf][m + 8][2 * t + 8];
            if (bn) {
                int ka = k0 + 2 * t, kb = ka + 8;
                float sc0 = ssc[ka], sh0 = ssh[ka];
                float sc1 = ssc[ka + 1], sh1 = ssh[ka + 1];
                float sc2 = ssc[kb], sh2 = ssh[kb];
                float sc3 = ssc[kb + 1], sh3 = ssh[kb + 1];
                f0.x = fmaxf(f0.x * sc0 + sh0, 0.f); f0.y = fmaxf(f0.y * sc1 + sh1, 0.f);
                f1.x = fmaxf(f1.x * sc0 + sh0, 0.f); f1.y = fmaxf(f1.y * sc1 + sh1, 0.f);
                f2.x = fmaxf(f2.x * sc2 + sh2, 0.f); f2.y = fmaxf(f2.y * sc3 + sh3, 0.f);
                f3.x = fmaxf(f3.x * sc2 + sh2, 0.f); f3.y = fmaxf(f3.y * sc3 + sh3, 0.f);
            }
            split2(f0, ah[mt][0], al[mt][0]);
            split2(f1, ah[mt][1], al[mt][1]);
            split2(f2, ah[mt][2], al[mt][2]);
            split2(f3, ah[mt][3], al[mt][3]);
        }
        #pragma unroll
        for (int nt = 0; nt < 8; nt++) {
            int n = warpN * 64 + nt * 8 + g;
            uint32_t bh[2], bl[2];
            bh[0] = *(uint32_t*)&WsH[buf][n][2 * t];
            bh[1] = *(uint32_t*)&WsH[buf][n][2 * t + 8];
            bl[0] = *(uint32_t*)&WsL[buf][n][2 * t];
            bl[1] = *(uint32_t*)&WsL[buf][n][2 * t + 8];
            #pragma unroll
            for (int mt = 0; mt < 2; mt++) {
                mma_f16(d[mt][nt], ah[mt], bh);
                mma_f16(d[mt][nt], al[mt], bh);
                mma_f16(d[mt][nt], ah[mt], bl);
            }
        }
    }

    #pragma unroll
    for (int mt = 0; mt < 2; mt++) {
        int r0 = rowBase + warpM * 32 + mt * 16 + g;
        int r1 = r0 + 8;
        #pragma unroll
        for (int nt = 0; nt < 8; nt++) {
            int c = warpN * 64 + nt * 8 + 2 * t;
            if (r0 < nrows)
                *(__half2*)&T[(size_t)r0 * 128 + c] = __floats2half2_rn(d[mt][nt][0], d[mt][nt][1]);
            if (r1 < nrows)
                *(__half2*)&T[(size_t)r1 * 128 + c] = __floats2half2_rn(d[mt][nt][2], d[mt][nt][3]);
        }
    }
}

// ---------------- finalize BN stats ----------------
__global__ void k_finalize_stats(const float* __restrict__ gam,
                                 const float* __restrict__ bet, int nrows)
{
    int f = threadIdx.x;
    float inv_n = 1.0f / (float)nrows;
    float m = g_sum[f] * inv_n;
    float v = g_sq[f] * inv_n - m * m;
    float istd = rsqrtf(v + EPSB);
    float sc = istd * gam[f];
    g_scale[f] = sc;
    g_shift[f] = bet[f] - m * sc;
    g_sum[f] = 0.f;
    g_sq [f] = 0.f;
}

// ---------------- CSR aggregation (HID=128), fp16 rows, 8-deep MLP (R14 form) ----------------
__global__ __launch_bounds__(256) void k_agg128(
    const int* __restrict__ rowptr, const int* __restrict__ col,
    const __half* __restrict__ T, const float* __restrict__ dinv,
    const float* __restrict__ b, float* __restrict__ U, int n)
{
    const uint2* T2 = (const uint2*)T;
    int lane   = threadIdx.x & 31;
    int warp   = (blockIdx.x * blockDim.x + threadIdx.x) >> 5;
    int nwarps = (gridDim.x * blockDim.x) >> 5;
    float4 bb  = *(const float4*)&b[lane * 4];

    float4 s4 = make_float4(0.f, 0.f, 0.f, 0.f);
    float4 q4 = make_float4(0.f, 0.f, 0.f, 0.f);

    for (int node = warp; node < n; node += nwarps) {
        int beg = rowptr[node], end = rowptr[node + 1];
        float dn = dinv[node];
        uint2 sv = T2[(size_t)node * 32 + lane];
        float2 sf0 = __half22float2(*(__half2*)&sv.x);
        float2 sf1 = __half22float2(*(__half2*)&sv.y);
        float4 acc  = make_float4(dn * sf0.x, dn * sf0.y, dn * sf1.x, dn * sf1.y);
        float4 acc2 = make_float4(0.f, 0.f, 0.f, 0.f);
        int e = beg;
        for (; e + 7 < end; e += 8) {
            int i0 = col[e],     i1 = col[e + 1], i2 = col[e + 2], i3 = col[e + 3];
            int i4 = col[e + 4], i5 = col[e + 5], i6 = col[e + 6], i7 = col[e + 7];
            float d0 = dinv[i0], d1 = dinv[i1], d2 = dinv[i2], d3 = dinv[i3];
            float d4 = dinv[i4], d5 = dinv[i5], d6 = dinv[i6], d7 = dinv[i7];
            uint2 r0 = T2[(size_t)i0 * 32 + lane];
            uint2 r1 = T2[(size_t)i1 * 32 + lane];
            uint2 r2 = T2[(size_t)i2 * 32 + lane];
            uint2 r3 = T2[(size_t)i3 * 32 + lane];
            uint2 r4 = T2[(size_t)i4 * 32 + lane];
            uint2 r5 = T2[(size_t)i5 * 32 + lane];
            uint2 r6 = T2[(size_t)i6 * 32 + lane];
            uint2 r7 = T2[(size_t)i7 * 32 + lane];
            #define ACC(A_, rv, dd) { \
                float2 f0_ = __half22float2(*(__half2*)&(rv).x); \
                float2 f1_ = __half22float2(*(__half2*)&(rv).y); \
                A_.x += (dd) * f0_.x; A_.y += (dd) * f0_.y; \
                A_.z += (dd) * f1_.x; A_.w += (dd) * f1_.y; }
            ACC(acc,  r0, d0) ACC(acc,  r1, d1) ACC(acc,  r2, d2) ACC(acc,  r3, d3)
            ACC(acc2, r4, d4) ACC(acc2, r5, d5) ACC(acc2, r6, d6) ACC(acc2, r7, d7)
        }
        for (; e < end; e++) {
            int i0 = col[e];
            float d0 = dinv[i0];
            uint2 rv = T2[(size_t)i0 * 32 + lane];
            ACC(acc, rv, d0)
        }
        #undef ACC
        acc.x += acc2.x; acc.y += acc2.y; acc.z += acc2.z; acc.w += acc2.w;

        float4 u = make_float4(acc.x * dn + bb.x, acc.y * dn + bb.y,
                               acc.z * dn + bb.z, acc.w * dn + bb.w);
        *(float4*)&U[(size_t)node * 128 + lane * 4] = u;
        s4.x += u.x; s4.y += u.y; s4.z += u.z; s4.w += u.w;
        q4.x += u.x * u.x; q4.y += u.y * u.y; q4.z += u.z * u.z; q4.w += u.w * u.w;
    }

    __shared__ float ss[128], sq[128];
    int t = threadIdx.x;
    if (t < 128) { ss[t] = 0.f; sq[t] = 0.f; }
    __syncthreads();
    int f = lane * 4;
    atomicAdd(&ss[f + 0], s4.x); atomicAdd(&sq[f + 0], q4.x);
    atomicAdd(&ss[f + 1], s4.y); atomicAdd(&sq[f + 1], q4.y);
    atomicAdd(&ss[f + 2], s4.z); atomicAdd(&sq[f + 2], q4.z);
    atomicAdd(&ss[f + 3], s4.w); atomicAdd(&sq[f + 3], q4.w);
    __syncthreads();
    if (t < 128) {
        atomicAdd(&g_sum[t], ss[t]);
        atomicAdd(&g_sq [t], sq[t]);
    }
}

// ---------------- layer-3 GEMM (128 -> 16): BN+ReLU fused; fp32 ----------------
__global__ __launch_bounds__(256) void k_gemm16(const float* __restrict__ A,
                                                const float* __restrict__ W,
                                                float* __restrict__ T, int nrows)
{
    __shared__ float Ws[128][16];
    __shared__ float ssc[128], ssh[128];
    for (int v = threadIdx.x; v < 128 * 16; v += blockDim.x)
        Ws[v >> 4][v & 15] = W[v];
    if (threadIdx.x < 128) {
        ssc[threadIdx.x] = g_scale[threadIdx.x];
        ssh[threadIdx.x] = g_shift[threadIdx.x];
    }
    __syncthreads();

    int row = blockIdx.x * blockDim.x + threadIdx.x;
    if (row >= nrows) return;
    float acc[16];
    #pragma unroll
    for (int c = 0; c < 16; c++) acc[c] = 0.f;

    const float4* ar = (const float4*)&A[(size_t)row * 128];
    #pragma unroll 4
    for (int k4 = 0; k4 < 32; k4++) {
        float4 x = ar[k4];
        int k = k4 * 4;
        x.x = fmaxf(x.x * ssc[k + 0] + ssh[k + 0], 0.f);
        x.y = fmaxf(x.y * ssc[k + 1] + ssh[k + 1], 0.f);
        x.z = fmaxf(x.z * ssc[k + 2] + ssh[k + 2], 0.f);
        x.w = fmaxf(x.w * ssc[k + 3] + ssh[k + 3], 0.f);
        #pragma unroll
        for (int c = 0; c < 16; c++)
            acc[c] += x.x * Ws[k][c] + x.y * Ws[k + 1][c]
                    + x.z * Ws[k + 2][c] + x.w * Ws[k + 3][c];
    }
    #pragma unroll
    for (int c = 0; c < 16; c += 4)
        *(float4*)&T[(size_t)row * 16 + c] =
            make_float4(acc[c], acc[c + 1], acc[c + 2], acc[c + 3]);
}

// ---------------- CSR aggregation (OUTD=16), fp32 ----------------
__global__ void k_agg16(const int* __restrict__ rowptr, const int* __restrict__ col,
                        const float* __restrict__ T, const float* __restrict__ dinv,
                        const float* __restrict__ b3, float* __restrict__ out, int n)
{
    int idx = blockIdx.x * blockDim.x + threadIdx.x;
    if (idx >= n * 4) return;
    int node = idx >> 2;
    int gp   = (idx & 3) * 4;
    float4 bb = *(const float4*)&b3[gp];

    int beg = rowptr[node], end = rowptr[node + 1];
    float dn = dinv[node];
    float4 tv = *(const float4*)&T[(size_t)node * 16 + gp];
    float4 acc = make_float4(dn * tv.x, dn * tv.y, dn * tv.z, dn * tv.w);
    int e = beg;
    for (; e + 3 < end; e += 4) {
        int s0 = col[e], s1 = col[e + 1], s2 = col[e + 2], s3 = col[e + 3];
        float d0 = dinv[s0], d1 = dinv[s1], d2 = dinv[s2], d3 = dinv[s3];
        float4 v0 = *(const float4*)&T[(size_t)s0 * 16 + gp];
        float4 v1 = *(const float4*)&T[(size_t)s1 * 16 + gp];
        float4 v2 = *(const float4*)&T[(size_t)s2 * 16 + gp];
        float4 v3 = *(const float4*)&T[(size_t)s3 * 16 + gp];
        acc.x += d0 * v0.x + d1 * v1.x + d2 * v2.x + d3 * v3.x;
        acc.y += d0 * v0.y + d1 * v1.y + d2 * v2.y + d3 * v3.y;
        acc.z += d0 * v0.z + d1 * v1.z + d2 * v2.z + d3 * v3.z;
        acc.w += d0 * v0.w + d1 * v1.w + d2 * v2.w + d3 * v3.w;
    }
    for (; e < end; e++) {
        int s = col[e];
        float d0 = dinv[s];
        float4 v = *(const float4*)&T[(size_t)s * 16 + gp];
        acc.x += d0 * v.x; acc.y += d0 * v.y; acc.z += d0 * v.z; acc.w += d0 * v.w;
    }
    *(float4*)&out[(size_t)node * 16 + gp] =
        make_float4(acc.x * dn + bb.x, acc.y * dn + bb.y,
                    acc.z * dn + bb.z, acc.w * dn + bb.w);
}

// ---------------- launch ----------------
extern "C" void kernel_launch(void* const* d_in, const int* in_sizes, int n_in,
                              void* d_out, int out_size)
{
    const float* x   = (const float*)d_in[0];
    const int*   ei  = (const int*)d_in[1];
    const float* W1  = (const float*)d_in[2];
    const float* b1  = (const float*)d_in[3];
    const float* g1  = (const float*)d_in[4];
    const float* be1 = (const float*)d_in[5];
    const float* W2  = (const float*)d_in[6];
    const float* b2  = (const float*)d_in[7];
    const float* g2  = (const float*)d_in[8];
    const float* be2 = (const float*)d_in[9];
    const float* W3  = (const float*)d_in[10];
    const float* b3  = (const float*)d_in[11];
    float*       out = (float*)d_out;

    int n = in_sizes[0] / IN_DIM;   // 50000
    int E = in_sizes[1] / 2;        // 800000

    int *cnt, *rowptr, *cursor, *col;
    float *dinv, *bufA, *bufB;
    __half *wt1h, *wt1l, *wt2h, *wt2l;
    cudaGetSymbolAddress((void**)&cnt,    g_cnt);
    cudaGetSymbolAddress((void**)&rowptr, g_rowptr);
    cudaGetSymbolAddress((void**)&cursor, g_cursor);
    cudaGetSymbolAddress((void**)&col,    g_col);
    cudaGetSymbolAddress((void**)&dinv,   g_dinv);
    cudaGetSymbolAddress((void**)&bufA,   g_bufA);
    cudaGetSymbolAddress((void**)&bufB,   g_bufB);
    cudaGetSymbolAddress((void**)&wt1h,   g_Wt1H);
    cudaGetSymbolAddress((void**)&wt1l,   g_Wt1L);
    cudaGetSymbolAddress((void**)&wt2h,   g_Wt2H);
    cudaGetSymbolAddress((void**)&wt2l,   g_Wt2L);
    __half* bufAh = (__half*)bufA;

    static cudaStream_t side = nullptr;
    static cudaEvent_t evFork = nullptr, evJoin = nullptr;
    if (side == nullptr) {
        cudaStreamCreateWithFlags(&side, cudaStreamNonBlocking);
        cudaEventCreateWithFlags(&evFork, cudaEventDisableTiming);
        cudaEventCreateWithFlags(&evJoin, cudaEventDisableTiming);
    }

    const int T256 = 256;
    int nb_n    = (n + T256 - 1) / T256;
    int nb_e    = (E + T256 - 1) / T256;
    int nb_rows = (n + 127) / 128;          // 391
    int nb_a16  = (n * 4 + T256 - 1) / T256;
    const int AGG_BLOCKS = 888;

    // fork: CSR build on side stream
    cudaEventRecord(evFork, 0);
    cudaStreamWaitEvent(side, evFork, 0);
    k_zero_cnt<<<nb_n, T256, 0, side>>>(cnt, n);
    k_hist    <<<nb_e, T256, 0, side>>>(ei, cnt, E);
    k_scan    <<<1, 1024, 0, side>>>(cnt, rowptr, cursor, dinv, n);
    k_fill    <<<nb_e, T256, 0, side>>>(ei, cursor, col, E);
    cudaEventRecord(evJoin, side);

    // weight prep (main stream, before gemm1)
    k_prepW<<<128, 256>>>(W1, W2);

    // ---- layer 1 ----
    k_gemm_hh<<<nb_rows, 256>>>(x, wt1h, wt1l, bufAh, n, IN_DIM, 0);

    cudaStreamWaitEvent(0, evJoin, 0);
    k_agg128<<<AGG_BLOCKS, 256>>>(rowptr, col, bufAh, dinv, b1, bufB, n);
    k_finalize_stats<<<1, 128>>>(g1, be1, n);

    // ---- layer 2 ----
    k_gemm_hh<<<nb_rows, 256>>>(bufB, wt2h, wt2l, bufAh, n, HID, 1);
    k_agg128 <<<AGG_BLOCKS, 256>>>(rowptr, col, bufAh, dinv, b2, bufB, n);
    k_finalize_stats<<<1, 128>>>(g2, be2, n);

    // ---- layer 3 ----
    k_gemm16<<<nb_n, 256>>>(bufB, W3, bufA, n);
    k_agg16 <<<nb_a16, T256>>>(rowptr, col, bufA, dinv, b3, out, n);
}